// round 4
// baseline (speedup 1.0000x reference)
#include <cuda_runtime.h>
#include <cuda_bf16.h>
#include <cstdint>

// Problem constants (fixed by the dataset)
#define M_ROWS 1024     // B*T_NEW
#define CDIM   2048
#define HHEADS 16
#define DHEAD  128
#define TPAST  2048
#define TNEW   128
#define TTOT   2176
#define BATCH  8

#define SA_STRIDE 40    // permuted-k A tile row stride (floats) -> conflict-free LDS.64
#define SB_STRIDE 136   // B tile row stride (floats) -> conflict-free scalar b-frag LDS
#define GEMM_BUF_FLOATS (128 * SA_STRIDE + 32 * SB_STRIDE)   // 9472
#define GEMM_SMEM_BYTES (2 * GEMM_BUF_FLOATS * 4)            // 75776

// Scratch (no cudaMalloc allowed)
__device__ float g_Q[M_ROWS * CDIM];
__device__ float g_attn[M_ROWS * CDIM];

__device__ __forceinline__ float tf32r(float x) {
    float y;
    asm("cvt.rna.tf32.f32 %0, %1;" : "=f"(y) : "f"(x));
    return y;
}

__device__ __forceinline__ void mma8(float* c, const float* a, const float* b) {
    const uint32_t* A = reinterpret_cast<const uint32_t*>(a);
    const uint32_t* B = reinterpret_cast<const uint32_t*>(b);
    asm volatile(
        "mma.sync.aligned.m16n8k8.row.col.f32.tf32.tf32.f32 "
        "{%0,%1,%2,%3}, {%4,%5,%6,%7}, {%8,%9}, {%0,%1,%2,%3};\n"
        : "+f"(c[0]), "+f"(c[1]), "+f"(c[2]), "+f"(c[3])
        : "r"(A[0]), "r"(A[1]), "r"(A[2]), "r"(A[3]), "r"(B[0]), "r"(B[1]));
}

__device__ __forceinline__ void cp_async16(uint32_t saddr, const void* gaddr) {
    asm volatile("cp.async.ca.shared.global [%0], [%1], 16;\n" :: "r"(saddr), "l"(gaddr));
}

// ---------------------------------------------------------------------------
// GEMM core, 512 threads: out(128x128 tile at bm,bn) = A @ W + bias
// Double-buffered smem, one sync per 32-k chunk, RNA-tf32 conversion on store.
// Warp grid 4x4, each warp computes 32x32 (2 m16 x 4 n8 tiles).
// ---------------------------------------------------------------------------
__device__ __forceinline__ void gemm_core(
    const float* __restrict__ A, const float* __restrict__ W,
    const float* __restrict__ bias, float* __restrict__ out,
    int scatter, int bm, int bn, float* smem)
{
    int tid = threadIdx.x;
    int lane = tid & 31, wid = tid >> 5;
    int g = lane >> 2, tg = lane & 3;
    int wr = (wid >> 2) * 32;  // warp row offset (0/32/64/96)
    int wc = (wid & 3) * 32;   // warp col offset

    float acc[2][4][4];
#pragma unroll
    for (int i = 0; i < 2; i++)
#pragma unroll
        for (int j = 0; j < 4; j++)
#pragma unroll
            for (int k = 0; k < 4; k++) acc[i][j][k] = 0.f;

    // load geometry (per thread: 2 float4 of A, 2 float4 of W per 32-k chunk)
    //   A: f = tid + i*512 -> row f>>3, cols (f&7)*4..+3
    //   W: f = tid + i*512 -> krow f>>5, cols (f&31)*4..+3
    float4 ra[2], rb[2];

#pragma unroll
    for (int i = 0; i < 2; i++) {
        int f = tid + i * 512;
        ra[i] = *reinterpret_cast<const float4*>(&A[(bm + (f >> 3)) * CDIM + (f & 7) * 4]);
        rb[i] = *reinterpret_cast<const float4*>(&W[(f >> 5) * CDIM + bn + (f & 31) * 4]);
    }

    int buf = 0;
    // store chunk 0 into buffer 0
    {
        float* sA = smem;
        float* sB = smem + 128 * SA_STRIDE;
#pragma unroll
        for (int i = 0; i < 2; i++) {
            int f = tid + i * 512;
            int r = f >> 3, c4 = (f & 7) * 4;
            float v[4] = {tf32r(ra[i].x), tf32r(ra[i].y), tf32r(ra[i].z), tf32r(ra[i].w)};
#pragma unroll
            for (int j = 0; j < 4; j++) {
                int k = c4 + j;
                int p = (k >> 3) * 8 + (k & 3) * 2 + ((k >> 2) & 1);
                sA[r * SA_STRIDE + p] = v[j];
            }
            int kr = f >> 5, cb = (f & 31) * 4;
            float4 w;
            w.x = tf32r(rb[i].x); w.y = tf32r(rb[i].y);
            w.z = tf32r(rb[i].z); w.w = tf32r(rb[i].w);
            *reinterpret_cast<float4*>(&sB[kr * SB_STRIDE + cb]) = w;
        }
    }
    __syncthreads();

    for (int kt = 0; kt < CDIM; kt += 32) {
        // prefetch next chunk into registers
        if (kt + 32 < CDIM) {
#pragma unroll
            for (int i = 0; i < 2; i++) {
                int f = tid + i * 512;
                ra[i] = *reinterpret_cast<const float4*>(
                    &A[(bm + (f >> 3)) * CDIM + kt + 32 + (f & 7) * 4]);
                rb[i] = *reinterpret_cast<const float4*>(
                    &W[(kt + 32 + (f >> 5)) * CDIM + bn + (f & 31) * 4]);
            }
        }

        float* sA = smem + buf * GEMM_BUF_FLOATS;
        float* sB = sA + 128 * SA_STRIDE;

        // compute 4 k8-steps on current buffer
#pragma unroll
        for (int ks = 0; ks < 4; ks++) {
            float2 a2[2][2];
#pragma unroll
            for (int mi = 0; mi < 2; mi++) {
                int r = wr + mi * 16;
                a2[mi][0] = *reinterpret_cast<const float2*>(
                    &sA[(r + g) * SA_STRIDE + ks * 8 + 2 * tg]);       // {a0,a2}
                a2[mi][1] = *reinterpret_cast<const float2*>(
                    &sA[(r + g + 8) * SA_STRIDE + ks * 8 + 2 * tg]);   // {a1,a3}
            }
            float b[4][2];
#pragma unroll
            for (int ni = 0; ni < 4; ni++) {
                int cn = wc + ni * 8 + g;
                b[ni][0] = sB[(ks * 8 + tg) * SB_STRIDE + cn];
                b[ni][1] = sB[(ks * 8 + tg + 4) * SB_STRIDE + cn];
            }
#pragma unroll
            for (int mi = 0; mi < 2; mi++) {
                float a[4] = {a2[mi][0].x, a2[mi][1].x, a2[mi][0].y, a2[mi][1].y};
#pragma unroll
                for (int ni = 0; ni < 4; ni++)
                    mma8(acc[mi][ni], a, b[ni]);
            }
        }

        // store prefetched chunk into the other buffer (safe: nobody reads it)
        if (kt + 32 < CDIM) {
            float* dA = smem + (buf ^ 1) * GEMM_BUF_FLOATS;
            float* dB = dA + 128 * SA_STRIDE;
#pragma unroll
            for (int i = 0; i < 2; i++) {
                int f = tid + i * 512;
                int r = f >> 3, c4 = (f & 7) * 4;
                float v[4] = {tf32r(ra[i].x), tf32r(ra[i].y), tf32r(ra[i].z), tf32r(ra[i].w)};
#pragma unroll
                for (int j = 0; j < 4; j++) {
                    int k = c4 + j;
                    int p = (k >> 3) * 8 + (k & 3) * 2 + ((k >> 2) & 1);
                    dA[r * SA_STRIDE + p] = v[j];
                }
                int kr = f >> 5, cb = (f & 31) * 4;
                float4 w;
                w.x = tf32r(rb[i].x); w.y = tf32r(rb[i].y);
                w.z = tf32r(rb[i].z); w.w = tf32r(rb[i].w);
                *reinterpret_cast<float4*>(&dB[kr * SB_STRIDE + cb]) = w;
            }
            __syncthreads();
            buf ^= 1;
        }
    }

#pragma unroll
    for (int mi = 0; mi < 2; mi++) {
#pragma unroll
        for (int ni = 0; ni < 4; ni++) {
            int row0 = bm + wr + mi * 16 + g;
            int col0 = bn + wc + ni * 8 + 2 * tg;
#pragma unroll
            for (int e = 0; e < 4; e++) {
                int row = row0 + ((e >= 2) ? 8 : 0);
                int col = col0 + (e & 1);
                float v = acc[mi][ni][e] + bias[col];
                if (!scatter) {
                    out[row * CDIM + col] = v;
                } else {
                    int b_ = row >> 7, t_ = row & 127;
                    int h_ = col >> 7, d_ = col & 127;
                    out[((b_ * HHEADS + h_) * TTOT + TPAST + t_) * DHEAD + d_] = v;
                }
            }
        }
    }
}

// ---------------------------------------------------------------------------
// Fused: 1D grid of 512 CTAs; role = bid&3 (0=Q,1=K,2=V GEMM, 3=past copy)
// Interleaved so copy CTAs overlap GEMM CTAs in every wave.
// ---------------------------------------------------------------------------
__global__ __launch_bounds__(512, 1) void fused_qkv_copy(
    const float* __restrict__ x,
    const float* __restrict__ Wq, const float* __restrict__ bq,
    const float* __restrict__ Wk, const float* __restrict__ bk,
    const float* __restrict__ Wv, const float* __restrict__ bv,
    const float* __restrict__ Kp, const float* __restrict__ Vp,
    float* __restrict__ gQ, float* __restrict__ Kout, float* __restrict__ Vout)
{
    extern __shared__ __align__(16) float smem[];
    int lin = blockIdx.x;
    int role = lin & 3;
    int t = lin >> 2;  // 0..127

    if (role == 3) {
        // past copy: one block per (b,h) slab, K and V interleaved
        const float4* Ks = reinterpret_cast<const float4*>(Kp) + (size_t)t * (TPAST * DHEAD / 4);
        const float4* Vs = reinterpret_cast<const float4*>(Vp) + (size_t)t * (TPAST * DHEAD / 4);
        float4* Kd = reinterpret_cast<float4*>(Kout) + (size_t)t * (TTOT * DHEAD / 4);
        float4* Vd = reinterpret_cast<float4*>(Vout) + (size_t)t * (TTOT * DHEAD / 4);
        for (int i = threadIdx.x; i < TPAST * DHEAD / 4; i += 512) {
            Kd[i] = Ks[i];
            Vd[i] = Vs[i];
        }
        return;
    }

    int bm = (t >> 4) * 128, bn = (t & 15) * 128;
    if (role == 0)      gemm_core(x, Wq, bq, gQ,   0, bm, bn, smem);
    else if (role == 1) gemm_core(x, Wk, bk, Kout, 1, bm, bn, smem);
    else                gemm_core(x, Wv, bv, Vout, 1, bm, bn, smem);
}

__global__ __launch_bounds__(512, 1) void gemm_wo(
    const float* __restrict__ A, const float* __restrict__ W,
    const float* __restrict__ bias, float* __restrict__ out)
{
    extern __shared__ __align__(16) float smem[];
    gemm_core(A, W, bias, out, 0, blockIdx.y * 128, blockIdx.x * 128, smem);
}

// ---------------------------------------------------------------------------
// Flash attention: one CTA per (b,h). 8 warps, each owns 16 query rows.
// V tile prefetched via cp.async (overlaps K load + S compute).
// ---------------------------------------------------------------------------
#define SMS 132  // padded smem row stride (floats)

__global__ __launch_bounds__(256) void attn_kernel(
    const float* __restrict__ Kc, const float* __restrict__ Vc)
{
    extern __shared__ float sm[];
    float* sQ = sm;                  // [128][SMS]
    float* sK = sm + 128 * SMS;      // K tile, then reused for P
    float* sV = sm + 2 * 128 * SMS;  // V tile (cp.async target, raw fp32)

    int tid = threadIdx.x, lane = tid & 31, wid = tid >> 5;
    int g = lane >> 2, tg = lane & 3;
    int bh = blockIdx.x, b = bh >> 4, h = bh & 15;
    const float qscale = 0.08838834764831845f;  // 1/sqrt(128)

    uint32_t svu = (uint32_t)__cvta_generic_to_shared(sV);

#pragma unroll
    for (int i = 0; i < 16; i++) {
        int f = tid + i * 256;
        int r = f >> 5, c4 = (f & 31) * 4;
        float4 v = *reinterpret_cast<const float4*>(&g_Q[(b * TNEW + r) * CDIM + h * DHEAD + c4]);
        sQ[r * SMS + c4 + 0] = tf32r(v.x * qscale);
        sQ[r * SMS + c4 + 1] = tf32r(v.y * qscale);
        sQ[r * SMS + c4 + 2] = tf32r(v.z * qscale);
        sQ[r * SMS + c4 + 3] = tf32r(v.w * qscale);
    }

    int r0 = wid * 16;
    float m0 = -1e30f, m1 = -1e30f, l0 = 0.f, l1 = 0.f;
    float O[16][4];
#pragma unroll
    for (int nt = 0; nt < 16; nt++)
#pragma unroll
        for (int e = 0; e < 4; e++) O[nt][e] = 0.f;

    const float* Kbh = Kc + (size_t)bh * TTOT * DHEAD;
    const float* Vbh = Vc + (size_t)bh * TTOT * DHEAD;

    for (int kt = 0; kt < 17; kt++) {
        // Prefetch V tile asynchronously (sV is dead until the PV phase)
#pragma unroll
        for (int i = 0; i < 16; i++) {
            int f = tid + i * 256;
            int r = f >> 5, c4 = (f & 31) * 4;
            cp_async16(svu + (uint32_t)(r * SMS + c4) * 4, &Vbh[(kt * 128 + r) * DHEAD + c4]);
        }
        asm volatile("cp.async.commit_group;\n");

        // K tile (RNA tf32)
#pragma unroll
        for (int i = 0; i < 16; i++) {
            int f = tid + i * 256;
            int r = f >> 5, c4 = (f & 31) * 4;
            float4 v = *reinterpret_cast<const float4*>(&Kbh[(kt * 128 + r) * DHEAD + c4]);
            sK[r * SMS + c4 + 0] = tf32r(v.x);
            sK[r * SMS + c4 + 1] = tf32r(v.y);
            sK[r * SMS + c4 + 2] = tf32r(v.z);
            sK[r * SMS + c4 + 3] = tf32r(v.w);
        }
        __syncthreads();

        float S[16][4];
#pragma unroll
        for (int nt = 0; nt < 16; nt++)
#pragma unroll
            for (int e = 0; e < 4; e++) S[nt][e] = 0.f;

#pragma unroll
        for (int ks = 0; ks < 16; ks++) {
            float a[4];
            a[0] = sQ[(r0 + g) * SMS + ks * 8 + tg];
            a[1] = sQ[(r0 + g + 8) * SMS + ks * 8 + tg];
            a[2] = sQ[(r0 + g) * SMS + ks * 8 + tg + 4];
            a[3] = sQ[(r0 + g + 8) * SMS + ks * 8 + tg + 4];
#pragma unroll
            for (int nt = 0; nt < 16; nt++) {
                float bb[2];
                bb[0] = sK[(nt * 8 + g) * SMS + ks * 8 + tg];
                bb[1] = sK[(nt * 8 + g) * SMS + ks * 8 + tg + 4];
                mma8(S[nt], a, bb);
            }
        }

        if (kt == 16) {
            int q0 = r0 + g, q1 = r0 + g + 8;
#pragma unroll
            for (int nt = 0; nt < 16; nt++) {
                int c0 = nt * 8 + 2 * tg;
                if (c0 > q0) S[nt][0] = -1e30f;
                if (c0 + 1 > q0) S[nt][1] = -1e30f;
                if (c0 > q1) S[nt][2] = -1e30f;
                if (c0 + 1 > q1) S[nt][3] = -1e30f;
            }
        }

        float mx0 = -1e30f, mx1 = -1e30f;
#pragma unroll
        for (int nt = 0; nt < 16; nt++) {
            mx0 = fmaxf(mx0, fmaxf(S[nt][0], S[nt][1]));
            mx1 = fmaxf(mx1, fmaxf(S[nt][2], S[nt][3]));
        }
        mx0 = fmaxf(mx0, __shfl_xor_sync(0xffffffffu, mx0, 1));
        mx0 = fmaxf(mx0, __shfl_xor_sync(0xffffffffu, mx0, 2));
        mx1 = fmaxf(mx1, __shfl_xor_sync(0xffffffffu, mx1, 1));
        mx1 = fmaxf(mx1, __shfl_xor_sync(0xffffffffu, mx1, 2));

        float mn0 = fmaxf(m0, mx0), mn1 = fmaxf(m1, mx1);
        float sc0 = __expf(m0 - mn0), sc1 = __expf(m1 - mn1);
        float rs0 = 0.f, rs1 = 0.f;
#pragma unroll
        for (int nt = 0; nt < 16; nt++) {
            S[nt][0] = __expf(S[nt][0] - mn0);
            S[nt][1] = __expf(S[nt][1] - mn0);
            S[nt][2] = __expf(S[nt][2] - mn1);
            S[nt][3] = __expf(S[nt][3] - mn1);
            rs0 += S[nt][0] + S[nt][1];
            rs1 += S[nt][2] + S[nt][3];
        }
        rs0 += __shfl_xor_sync(0xffffffffu, rs0, 1);
        rs0 += __shfl_xor_sync(0xffffffffu, rs0, 2);
        rs1 += __shfl_xor_sync(0xffffffffu, rs1, 1);
        rs1 += __shfl_xor_sync(0xffffffffu, rs1, 2);

        l0 = l0 * sc0 + rs0;
        l1 = l1 * sc1 + rs1;
#pragma unroll
        for (int nt = 0; nt < 16; nt++) {
            O[nt][0] *= sc0; O[nt][1] *= sc0;
            O[nt][2] *= sc1; O[nt][3] *= sc1;
        }
        m0 = mn0; m1 = mn1;

        __syncthreads();  // all warps done reading sK(K)

        // store P into sK (reuse)
#pragma unroll
        for (int nt = 0; nt < 16; nt++) {
            sK[(r0 + g) * SMS + nt * 8 + 2 * tg]         = tf32r(S[nt][0]);
            sK[(r0 + g) * SMS + nt * 8 + 2 * tg + 1]     = tf32r(S[nt][1]);
            sK[(r0 + g + 8) * SMS + nt * 8 + 2 * tg]     = tf32r(S[nt][2]);
            sK[(r0 + g + 8) * SMS + nt * 8 + 2 * tg + 1] = tf32r(S[nt][3]);
        }

        asm volatile("cp.async.wait_group 0;\n");
        __syncthreads();  // P + V visible to all

#pragma unroll
        for (int ks = 0; ks < 16; ks++) {
            float a[4];
            a[0] = sK[(r0 + g) * SMS + ks * 8 + tg];
            a[1] = sK[(r0 + g + 8) * SMS + ks * 8 + tg];
            a[2] = sK[(r0 + g) * SMS + ks * 8 + tg + 4];
            a[3] = sK[(r0 + g + 8) * SMS + ks * 8 + tg + 4];
#pragma unroll
            for (int nt = 0; nt < 16; nt++) {
                float bb[2];
                bb[0] = sV[(ks * 8 + tg) * SMS + nt * 8 + g];
                bb[1] = sV[(ks * 8 + tg + 4) * SMS + nt * 8 + g];
                mma8(O[nt], a, bb);
            }
        }
        __syncthreads();  // before next iter overwrites sK / issues new cp.async to sV
    }

    float i0 = 1.f / l0, i1 = 1.f / l1;
#pragma unroll
    for (int nt = 0; nt < 16; nt++) {
        int col = h * DHEAD + nt * 8 + 2 * tg;
        float* o0 = &g_attn[(b * TNEW + r0 + g) * CDIM + col];
        o0[0] = O[nt][0] * i0;
        o0[1] = O[nt][1] * i0;
        float* o1 = &g_attn[(b * TNEW + r0 + g + 8) * CDIM + col];
        o1[0] = O[nt][2] * i1;
        o1[1] = O[nt][3] * i1;
    }
}

// ---------------------------------------------------------------------------
extern "C" void kernel_launch(void* const* d_in, const int* in_sizes, int n_in,
                              void* d_out, int out_size)
{
    const float* x  = (const float*)d_in[0];
    const float* Kp = (const float*)d_in[1];
    const float* Vp = (const float*)d_in[2];
    const float* Wq = (const float*)d_in[3];
    const float* bq = (const float*)d_in[4];
    const float* Wk = (const float*)d_in[5];
    const float* bk = (const float*)d_in[6];
    const float* Wv = (const float*)d_in[7];
    const float* bv = (const float*)d_in[8];
    const float* Wo = (const float*)d_in[9];
    const float* bo = (const float*)d_in[10];

    float* out  = (float*)d_out;
    float* Kout = out + (size_t)M_ROWS * CDIM;
    float* Vout = Kout + (size_t)BATCH * HHEADS * TTOT * DHEAD;

    float *gQ, *gA;
    cudaGetSymbolAddress((void**)&gQ, g_Q);
    cudaGetSymbolAddress((void**)&gA, g_attn);

    const int attn_smem = 3 * 128 * SMS * sizeof(float);  // 202,752 B
    cudaFuncSetAttribute(attn_kernel, cudaFuncAttributeMaxDynamicSharedMemorySize, attn_smem);
    cudaFuncSetAttribute(fused_qkv_copy, cudaFuncAttributeMaxDynamicSharedMemorySize, GEMM_SMEM_BYTES);
    cudaFuncSetAttribute(gemm_wo, cudaFuncAttributeMaxDynamicSharedMemorySize, GEMM_SMEM_BYTES);

    // Phase 1: fused QKV projections + past-KV copy, role-interleaved
    fused_qkv_copy<<<512, 512, GEMM_SMEM_BYTES>>>(x, Wq, bq, Wk, bk, Wv, bv,
                                                  Kp, Vp, gQ, Kout, Vout);

    // Phase 2: attention
    attn_kernel<<<BATCH * HHEADS, 256, attn_smem>>>(Kout, Vout);

    // Phase 3: output projection
    dim3 gg(CDIM / 128, M_ROWS / 128);  // (16, 8)
    gemm_wo<<<gg, 512, GEMM_SMEM_BYTES>>>(gA, Wo, bo, out);
}

// round 6
// speedup vs baseline: 1.1441x; 1.1441x over previous
#include <cuda_runtime.h>
#include <cuda_bf16.h>
#include <cstdint>

// Problem constants (fixed by the dataset)
#define M_ROWS 1024     // B*T_NEW
#define CDIM   2048
#define HHEADS 16
#define DHEAD  128
#define TPAST  2048
#define TNEW   128
#define TTOT   2176
#define BATCH  8

// ---------------------------------------------------------------------------
// Scratch (no cudaMalloc allowed)
// ---------------------------------------------------------------------------
__device__ float g_Q[M_ROWS * CDIM];       // 8 MB
__device__ float g_attn[M_ROWS * CDIM];    // 8 MB (tf32-pre-rounded by attn)
__device__ float g_xr[M_ROWS * CDIM];      // 8 MB  x, tf32-pre-rounded
__device__ float g_WT[4ull * CDIM * CDIM]; // 64 MB Wq/Wk/Wv/Wo transposed+rounded

__device__ __forceinline__ float tf32r(float x) {
    float y;
    asm("cvt.rna.tf32.f32 %0, %1;" : "=f"(y) : "f"(x));
    return y;
}
__device__ __forceinline__ void mma8(float* c, const float* a, const float* b) {
    const uint32_t* A = reinterpret_cast<const uint32_t*>(a);
    const uint32_t* B = reinterpret_cast<const uint32_t*>(b);
    asm volatile(
        "mma.sync.aligned.m16n8k8.row.col.f32.tf32.tf32.f32 "
        "{%0,%1,%2,%3}, {%4,%5,%6,%7}, {%8,%9}, {%0,%1,%2,%3};\n"
        : "+f"(c[0]), "+f"(c[1]), "+f"(c[2]), "+f"(c[3])
        : "r"(A[0]), "r"(A[1]), "r"(A[2]), "r"(A[3]), "r"(B[0]), "r"(B[1]));
}
__device__ __forceinline__ void cp_async16(uint32_t saddr, const void* gaddr) {
    asm volatile("cp.async.ca.shared.global [%0], [%1], 16;\n" :: "r"(saddr), "l"(gaddr));
}
#define SWZ128(o) ((o) ^ (((o) >> 3) & 0x70))

// ---------------------------------------------------------------------------
// Prep kernel: z<4 -> transpose+round W_z into g_WT slab; z==4 -> round x
// grid (64,64,5), block (32,8)
// ---------------------------------------------------------------------------
__global__ void prep_kernel(
    const float* __restrict__ Wq, const float* __restrict__ Wk,
    const float* __restrict__ Wv, const float* __restrict__ Wo,
    const float* __restrict__ x)
{
    int z = blockIdx.z;
    int tx = threadIdx.x, ty = threadIdx.y;
    if (z == 4) {
        int idx = blockIdx.y * 64 + blockIdx.x;
        if (idx >= 1024) return;                       // 1024 blocks x 2048 floats = 2M
        size_t base = (size_t)idx * 2048 + (ty * 32 + tx) * 8;
        const float4* src = reinterpret_cast<const float4*>(x + base);
        float4* dst = reinterpret_cast<float4*>(g_xr + base);
#pragma unroll
        for (int j = 0; j < 2; j++) {
            float4 v = src[j];
            v.x = tf32r(v.x); v.y = tf32r(v.y); v.z = tf32r(v.z); v.w = tf32r(v.w);
            dst[j] = v;
        }
        return;
    }
    const float* W = (z == 0) ? Wq : (z == 1) ? Wk : (z == 2) ? Wv : Wo;
    float* WT = g_WT + (size_t)z * CDIM * CDIM;
    __shared__ float t[32][33];
    int x0 = blockIdx.x * 32, y0 = blockIdx.y * 32;  // y0 = k, x0 = n
#pragma unroll
    for (int j = 0; j < 4; j++)
        t[ty + 8 * j][tx] = tf32r(W[(size_t)(y0 + ty + 8 * j) * CDIM + x0 + tx]);
    __syncthreads();
#pragma unroll
    for (int j = 0; j < 4; j++)
        WT[(size_t)(x0 + ty + 8 * j) * CDIM + y0 + tx] = t[tx][ty + 8 * j];
}

// ---------------------------------------------------------------------------
// cp.async 2-stage tf32 GEMM: D[m][n] = sum_k Ap[m][k]*Bp[n][k] + bias[n]
// Ap, Bp both K-contiguous, pre-rounded RNA tf32.
// 256 threads, CTA tile 128x128, warp tile 64x32, k-chunk 32.
// smem: 2 stages x (A 128x32 + B 128x32) fp32, XOR-swizzled 128B rows = 64 KB.
// ---------------------------------------------------------------------------
#define GSTAGE_FLOATS 8192            // 32 KB per stage (A 4096 + B 4096)
#define GEMM_SMEM_BYTES (2 * GSTAGE_FLOATS * 4)   // 65536
#define NCH 64                        // 2048 / 32

__device__ __forceinline__ void fill_chunk(
    uint32_t sbase, int st, const float* __restrict__ Ap,
    const float* __restrict__ Bp, int kt)
{
    uint32_t base = sbase + st * (GSTAGE_FLOATS * 4);
    int tid = threadIdx.x;
#pragma unroll
    for (int i = 0; i < 4; i++) {
        int f = tid + i * 256;            // 0..1023
        int r = f >> 3, k4 = f & 7;
        uint32_t off = SWZ128((uint32_t)(r * 128 + k4 * 16));
        cp_async16(base + off,         Ap + (size_t)r * CDIM + kt + k4 * 4);
        cp_async16(base + 16384 + off, Bp + (size_t)r * CDIM + kt + k4 * 4);
    }
    asm volatile("cp.async.commit_group;\n");
}

__device__ __forceinline__ void gemm_core(
    const float* __restrict__ Ap, const float* __restrict__ Bp,
    const float* __restrict__ bias, float* __restrict__ out,
    int scatter, int bm, int bn, float* smem)
{
    int tid = threadIdx.x;
    int lane = tid & 31, wid = tid >> 5;
    int g = lane >> 2, tg = lane & 3;
    int wr = (wid >> 2) * 64;  // warp row offset (0/64)
    int wc = (wid & 3) * 32;   // warp col offset
    uint32_t sbase = (uint32_t)__cvta_generic_to_shared(smem);

    float acc[4][4][4];
#pragma unroll
    for (int i = 0; i < 4; i++)
#pragma unroll
        for (int j = 0; j < 4; j++)
#pragma unroll
            for (int k = 0; k < 4; k++) acc[i][j][k] = 0.f;

    fill_chunk(sbase, 0, Ap, Bp, 0);
    fill_chunk(sbase, 1, Ap, Bp, 32);
    asm volatile("cp.async.wait_group 1;\n");
    __syncthreads();

    int xv = g << 2;   // float-index XOR for swizzle (bank-spreading)

    for (int i = 0; i < NCH; i++) {
        int st = i & 1;
        const float* sA = smem + st * GSTAGE_FLOATS;
        const float* sB = sA + 4096;

#pragma unroll
        for (int ks = 0; ks < 4; ks++) {
            int c0 = (ks * 8 + tg) ^ xv;        // float index within 32-float row
            int c1 = (ks * 8 + tg + 4) ^ xv;
            float a[4][4];
#pragma unroll
            for (int mi = 0; mi < 4; mi++) {
                int r0 = (wr + mi * 16 + g) * 32;
                int r1 = r0 + 8 * 32;
                a[mi][0] = sA[r0 + c0];
                a[mi][1] = sA[r1 + c0];
                a[mi][2] = sA[r0 + c1];
                a[mi][3] = sA[r1 + c1];
            }
            float b[4][2];
#pragma unroll
            for (int ni = 0; ni < 4; ni++) {
                int rn = (wc + ni * 8 + g) * 32;
                b[ni][0] = sB[rn + c0];
                b[ni][1] = sB[rn + c1];
            }
#pragma unroll
            for (int mi = 0; mi < 4; mi++)
#pragma unroll
                for (int ni = 0; ni < 4; ni++)
                    mma8(acc[mi][ni], a[mi], b[ni]);
        }

        __syncthreads();   // all warps done reading stage st
        if (i + 2 < NCH) fill_chunk(sbase, st, Ap, Bp, (i + 2) * 32);
        if (i + 1 < NCH) {
            if (i + 2 < NCH) asm volatile("cp.async.wait_group 1;\n");
            else             asm volatile("cp.async.wait_group 0;\n");
            __syncthreads();
        }
    }

#pragma unroll
    for (int mi = 0; mi < 4; mi++) {
#pragma unroll
        for (int ni = 0; ni < 4; ni++) {
            int row0 = bm + wr + mi * 16 + g;
            int col0 = bn + wc + ni * 8 + 2 * tg;
#pragma unroll
            for (int e = 0; e < 4; e++) {
                int row = row0 + ((e >= 2) ? 8 : 0);
                int col = col0 + (e & 1);
                float v = acc[mi][ni][e] + bias[col];
                if (!scatter) {
                    out[(size_t)row * CDIM + col] = v;
                } else {
                    int b_ = row >> 7, t_ = row & 127;
                    int h_ = col >> 7, d_ = col & 127;
                    out[((size_t)(b_ * HHEADS + h_) * TTOT + TPAST + t_) * DHEAD + d_] = v;
                }
            }
        }
    }
}

// ---------------------------------------------------------------------------
// Fused: 1D grid of 512 CTAs; role = bid&3 (0=Q,1=K,2=V GEMM, 3=past copy)
// ---------------------------------------------------------------------------
__global__ __launch_bounds__(256, 2) void fused_qkv_copy(
    const float* __restrict__ bq, const float* __restrict__ bk, const float* __restrict__ bv,
    const float* __restrict__ Kp, const float* __restrict__ Vp,
    float* __restrict__ gQ, float* __restrict__ Kout, float* __restrict__ Vout)
{
    extern __shared__ __align__(16) float smem[];
    int lin = blockIdx.x;
    int role = lin & 3;
    int t = lin >> 2;  // 0..127

    if (role == 3) {
        const float4* Ks = reinterpret_cast<const float4*>(Kp) + (size_t)t * (TPAST * DHEAD / 4);
        const float4* Vs = reinterpret_cast<const float4*>(Vp) + (size_t)t * (TPAST * DHEAD / 4);
        float4* Kd = reinterpret_cast<float4*>(Kout) + (size_t)t * (TTOT * DHEAD / 4);
        float4* Vd = reinterpret_cast<float4*>(Vout) + (size_t)t * (TTOT * DHEAD / 4);
        for (int i = threadIdx.x; i < TPAST * DHEAD / 4; i += 256) {
            Kd[i] = Ks[i];
            Vd[i] = Vs[i];
        }
        return;
    }

    int bm = (t >> 4) * 128, bn = (t & 15) * 128;
    const float* Ap = g_xr + (size_t)bm * CDIM;
    const float* Bp = g_WT + (size_t)role * CDIM * CDIM + (size_t)bn * CDIM;
    if (role == 0)      gemm_core(Ap, Bp, bq, gQ,   0, bm, bn, smem);
    else if (role == 1) gemm_core(Ap, Bp, bk, Kout, 1, bm, bn, smem);
    else                gemm_core(Ap, Bp, bv, Vout, 1, bm, bn, smem);
}

__global__ __launch_bounds__(256, 2) void gemm_wo(
    const float* __restrict__ bo, float* __restrict__ out)
{
    extern __shared__ __align__(16) float smem[];
    int t = blockIdx.x;
    int bm = (t >> 4) * 128, bn = (t & 15) * 128;
    gemm_core(g_attn + (size_t)bm * CDIM,
              g_WT + 3ull * CDIM * CDIM + (size_t)bn * CDIM,
              bo, out, 0, bm, bn, smem);
}

// ---------------------------------------------------------------------------
// Flash attention: one CTA per (b,h). 8 warps, each owns 16 query rows.
// V tile prefetched via cp.async. Outputs tf32-pre-rounded for the Wo GEMM.
// ---------------------------------------------------------------------------
#define SMS 132  // padded smem row stride (floats)

__global__ __launch_bounds__(256) void attn_kernel(
    const float* __restrict__ Kc, const float* __restrict__ Vc)
{
    extern __shared__ float sm[];
    float* sQ = sm;
    float* sK = sm + 128 * SMS;
    float* sV = sm + 2 * 128 * SMS;

    int tid = threadIdx.x, lane = tid & 31, wid = tid >> 5;
    int g = lane >> 2, tg = lane & 3;
    int bh = blockIdx.x, b = bh >> 4, h = bh & 15;
    const float qscale = 0.08838834764831845f;

    uint32_t svu = (uint32_t)__cvta_generic_to_shared(sV);

#pragma unroll
    for (int i = 0; i < 16; i++) {
        int f = tid + i * 256;
        int r = f >> 5, c4 = (f & 31) * 4;
        float4 v = *reinterpret_cast<const float4*>(&g_Q[(b * TNEW + r) * CDIM + h * DHEAD + c4]);
        sQ[r * SMS + c4 + 0] = tf32r(v.x * qscale);
        sQ[r * SMS + c4 + 1] = tf32r(v.y * qscale);
        sQ[r * SMS + c4 + 2] = tf32r(v.z * qscale);
        sQ[r * SMS + c4 + 3] = tf32r(v.w * qscale);
    }

    int r0 = wid * 16;
    float m0 = -1e30f, m1 = -1e30f, l0 = 0.f, l1 = 0.f;
    float O[16][4];
#pragma unroll
    for (int nt = 0; nt < 16; nt++)
#pragma unroll
        for (int e = 0; e < 4; e++) O[nt][e] = 0.f;

    const float* Kbh = Kc + (size_t)bh * TTOT * DHEAD;
    const float* Vbh = Vc + (size_t)bh * TTOT * DHEAD;

    for (int kt = 0; kt < 17; kt++) {
#pragma unroll
        for (int i = 0; i < 16; i++) {
            int f = tid + i * 256;
            int r = f >> 5, c4 = (f & 31) * 4;
            cp_async16(svu + (uint32_t)(r * SMS + c4) * 4, &Vbh[(kt * 128 + r) * DHEAD + c4]);
        }
        asm volatile("cp.async.commit_group;\n");

#pragma unroll
        for (int i = 0; i < 16; i++) {
            int f = tid + i * 256;
            int r = f >> 5, c4 = (f & 31) * 4;
            float4 v = *reinterpret_cast<const float4*>(&Kbh[(kt * 128 + r) * DHEAD + c4]);
            sK[r * SMS + c4 + 0] = tf32r(v.x);
            sK[r * SMS + c4 + 1] = tf32r(v.y);
            sK[r * SMS + c4 + 2] = tf32r(v.z);
            sK[r * SMS + c4 + 3] = tf32r(v.w);
        }
        __syncthreads();

        float S[16][4];
#pragma unroll
        for (int nt = 0; nt < 16; nt++)
#pragma unroll
            for (int e = 0; e < 4; e++) S[nt][e] = 0.f;

#pragma unroll
        for (int ks = 0; ks < 16; ks++) {
            float a[4];
            a[0] = sQ[(r0 + g) * SMS + ks * 8 + tg];
            a[1] = sQ[(r0 + g + 8) * SMS + ks * 8 + tg];
            a[2] = sQ[(r0 + g) * SMS + ks * 8 + tg + 4];
            a[3] = sQ[(r0 + g + 8) * SMS + ks * 8 + tg + 4];
#pragma unroll
            for (int nt = 0; nt < 16; nt++) {
                float bb[2];
                bb[0] = sK[(nt * 8 + g) * SMS + ks * 8 + tg];
                bb[1] = sK[(nt * 8 + g) * SMS + ks * 8 + tg + 4];
                mma8(S[nt], a, bb);
            }
        }

        if (kt == 16) {
            int q0 = r0 + g, q1 = r0 + g + 8;
#pragma unroll
            for (int nt = 0; nt < 16; nt++) {
                int c0 = nt * 8 + 2 * tg;
                if (c0 > q0) S[nt][0] = -1e30f;
                if (c0 + 1 > q0) S[nt][1] = -1e30f;
                if (c0 > q1) S[nt][2] = -1e30f;
                if (c0 + 1 > q1) S[nt][3] = -1e30f;
            }
        }

        float mx0 = -1e30f, mx1 = -1e30f;
#pragma unroll
        for (int nt = 0; nt < 16; nt++) {
            mx0 = fmaxf(mx0, fmaxf(S[nt][0], S[nt][1]));
            mx1 = fmaxf(mx1, fmaxf(S[nt][2], S[nt][3]));
        }
        mx0 = fmaxf(mx0, __shfl_xor_sync(0xffffffffu, mx0, 1));
        mx0 = fmaxf(mx0, __shfl_xor_sync(0xffffffffu, mx0, 2));
        mx1 = fmaxf(mx1, __shfl_xor_sync(0xffffffffu, mx1, 1));
        mx1 = fmaxf(mx1, __shfl_xor_sync(0xffffffffu, mx1, 2));

        float mn0 = fmaxf(m0, mx0), mn1 = fmaxf(m1, mx1);
        float sc0 = __expf(m0 - mn0), sc1 = __expf(m1 - mn1);
        float rs0 = 0.f, rs1 = 0.f;
#pragma unroll
        for (int nt = 0; nt < 16; nt++) {
            S[nt][0] = __expf(S[nt][0] - mn0);
            S[nt][1] = __expf(S[nt][1] - mn0);
            S[nt][2] = __expf(S[nt][2] - mn1);
            S[nt][3] = __expf(S[nt][3] - mn1);
            rs0 += S[nt][0] + S[nt][1];
            rs1 += S[nt][2] + S[nt][3];
        }
        rs0 += __shfl_xor_sync(0xffffffffu, rs0, 1);
        rs0 += __shfl_xor_sync(0xffffffffu, rs0, 2);
        rs1 += __shfl_xor_sync(0xffffffffu, rs1, 1);
        rs1 += __shfl_xor_sync(0xffffffffu, rs1, 2);

        l0 = l0 * sc0 + rs0;
        l1 = l1 * sc1 + rs1;
#pragma unroll
        for (int nt = 0; nt < 16; nt++) {
            O[nt][0] *= sc0; O[nt][1] *= sc0;
            O[nt][2] *= sc1; O[nt][3] *= sc1;
        }
        m0 = mn0; m1 = mn1;

        __syncthreads();

#pragma unroll
        for (int nt = 0; nt < 16; nt++) {
            sK[(r0 + g) * SMS + nt * 8 + 2 * tg]         = tf32r(S[nt][0]);
            sK[(r0 + g) * SMS + nt * 8 + 2 * tg + 1]     = tf32r(S[nt][1]);
            sK[(r0 + g + 8) * SMS + nt * 8 + 2 * tg]     = tf32r(S[nt][2]);
            sK[(r0 + g + 8) * SMS + nt * 8 + 2 * tg + 1] = tf32r(S[nt][3]);
        }

        asm volatile("cp.async.wait_group 0;\n");
        __syncthreads();

#pragma unroll
        for (int ks = 0; ks < 16; ks++) {
            float a[4];
            a[0] = sK[(r0 + g) * SMS + ks * 8 + tg];
            a[1] = sK[(r0 + g + 8) * SMS + ks * 8 + tg];
            a[2] = sK[(r0 + g) * SMS + ks * 8 + tg + 4];
            a[3] = sK[(r0 + g + 8) * SMS + ks * 8 + tg + 4];
#pragma unroll
            for (int nt = 0; nt < 16; nt++) {
                float bb[2];
                bb[0] = sV[(ks * 8 + tg) * SMS + nt * 8 + g];
                bb[1] = sV[(ks * 8 + tg + 4) * SMS + nt * 8 + g];
                mma8(O[nt], a, bb);
            }
        }
        __syncthreads();
    }

    float i0 = 1.f / l0, i1 = 1.f / l1;
#pragma unroll
    for (int nt = 0; nt < 16; nt++) {
        int col = h * DHEAD + nt * 8 + 2 * tg;
        float* o0 = &g_attn[(b * TNEW + r0 + g) * CDIM + col];
        o0[0] = tf32r(O[nt][0] * i0);
        o0[1] = tf32r(O[nt][1] * i0);
        float* o1 = &g_attn[(b * TNEW + r0 + g + 8) * CDIM + col];
        o1[0] = tf32r(O[nt][2] * i1);
        o1[1] = tf32r(O[nt][3] * i1);
    }
}

// ---------------------------------------------------------------------------
extern "C" void kernel_launch(void* const* d_in, const int* in_sizes, int n_in,
                              void* d_out, int out_size)
{
    const float* x  = (const float*)d_in[0];
    const float* Kp = (const float*)d_in[1];
    const float* Vp = (const float*)d_in[2];
    const float* Wq = (const float*)d_in[3];
    const float* bq = (const float*)d_in[4];
    const float* Wk = (const float*)d_in[5];
    const float* bk = (const float*)d_in[6];
    const float* Wv = (const float*)d_in[7];
    const float* bv = (const float*)d_in[8];
    const float* Wo = (const float*)d_in[9];
    const float* bo = (const float*)d_in[10];

    float* out  = (float*)d_out;
    float* Kout = out + (size_t)M_ROWS * CDIM;
    float* Vout = Kout + (size_t)BATCH * HHEADS * TTOT * DHEAD;

    float* gQ;
    cudaGetSymbolAddress((void**)&gQ, g_Q);

    const int attn_smem = 3 * 128 * SMS * sizeof(float);  // 202,752 B
    cudaFuncSetAttribute(attn_kernel, cudaFuncAttributeMaxDynamicSharedMemorySize, attn_smem);
    cudaFuncSetAttribute(fused_qkv_copy, cudaFuncAttributeMaxDynamicSharedMemorySize, GEMM_SMEM_BYTES);
    cudaFuncSetAttribute(gemm_wo, cudaFuncAttributeMaxDynamicSharedMemorySize, GEMM_SMEM_BYTES);

    // Phase 0: transpose+round weights, round x
    prep_kernel<<<dim3(64, 64, 5), dim3(32, 8)>>>(Wq, Wk, Wv, Wo, x);

    // Phase 1: fused QKV GEMMs + past-KV copy (role-interleaved)
    fused_qkv_copy<<<512, 256, GEMM_SMEM_BYTES>>>(bq, bk, bv, Kp, Vp, gQ, Kout, Vout);

    // Phase 2: attention
    attn_kernel<<<BATCH * HHEADS, 256, attn_smem>>>(Kout, Vout);

    // Phase 3: output projection
    gemm_wo<<<128, 256, GEMM_SMEM_BYTES>>>(bo, out);
}